// round 5
// baseline (speedup 1.0000x reference)
#include <cuda_runtime.h>
#include <cuda_fp16.h>
#include <cstdint>

// Problem constants
#define NQ      16384      // B*H*W
#define NEG     4096       // embeddings per group
#define GR      4
#define KD      64         // embedding dim
#define TQ      128        // queries per block
#define NT      128        // e per tile
#define NTILES  (NEG / NT) // 32
#define CAP     64         // candidate capacity per row

typedef unsigned long long ull;

// ---- device scratch (static, no allocation) ----
__device__ int      g_idx[NQ * GR];               // final argmax indices
__device__ float    g_embn[NEG * GR * KD];        // normalized embedding (fp32)
__device__ int      g_embh[GR * NTILES * 4096];   // fp16 swizzled 16KB tile images
__device__ int      g_hist[NEG];                  // histogram of idx[:, 3]
__device__ int      g_cnt[NQ * GR];               // candidate counts
__device__ int      g_cand[NQ * GR * CAP];        // candidate lists

// ============================================================================
// PTX helpers (base-target: ldmatrix sm_75+, mma.sync sm_80+, cp.async sm_80+)
// ============================================================================
__device__ __forceinline__ uint32_t smem_u32(const void* p) {
    uint32_t a;
    asm("{ .reg .u64 t; cvta.to.shared.u64 t, %1; cvt.u32.u64 %0, t; }"
        : "=r"(a) : "l"(p));
    return a;
}
#define LDSM_X4(r, addr) \
    asm volatile("ldmatrix.sync.aligned.m8n8.x4.shared.b16 {%0,%1,%2,%3}, [%4];" \
        : "=r"((r)[0]), "=r"((r)[1]), "=r"((r)[2]), "=r"((r)[3]) : "r"(addr))

// fp16-accumulate HMMA
__device__ __forceinline__ void mma16816_f16(uint32_t* c, const uint32_t* a,
                                             const uint32_t* b) {
    asm volatile("mma.sync.aligned.m16n8k16.row.col.f16.f16.f16.f16 "
        "{%0,%1}, {%2,%3,%4,%5}, {%6,%7}, {%0,%1};"
        : "+r"(c[0]), "+r"(c[1])
        : "r"(a[0]), "r"(a[1]), "r"(a[2]), "r"(a[3]), "r"(b[0]), "r"(b[1]));
}
__device__ __forceinline__ void cp16(uint32_t dst, const void* src) {
    asm volatile("cp.async.cg.shared.global [%0], [%1], 16;"
                 :: "r"(dst), "l"(src));
}
__device__ __forceinline__ void cp_commit() {
    asm volatile("cp.async.commit_group;" ::: "memory");
}
__device__ __forceinline__ void cp_wait0() {
    asm volatile("cp.async.wait_group 0;" ::: "memory");
}

// ============================================================================
// init: zero counters / histogram
// ============================================================================
__global__ void init_kernel()
{
    int i = blockIdx.x * 256 + threadIdx.x;
    if (i < NQ * GR) g_cnt[i] = 0;
    if (i < NEG)     g_hist[i] = 0;
}

// ============================================================================
// emb prep: normalize rows -> g_embn(fp32); fp16 XOR-swizzled tile images.
// Tile image: 128 e-rows x 64 k halfs; half2 idx = er*32 + ((kblk^(er&7))<<2)
//   + pair-in-block, kblk = k/8. One warp per embedding row.
// ============================================================================
__global__ void embprep_kernel(const float* __restrict__ emb)
{
    int warp = (blockIdx.x * blockDim.x + threadIdx.x) >> 5;
    int lane = threadIdx.x & 31;
    if (warp >= NEG * GR) return;
    float2 v = reinterpret_cast<const float2*>(emb + (size_t)warp * KD)[lane];
    float s = v.x * v.x + v.y * v.y;
    #pragma unroll
    for (int m = 16; m >= 1; m >>= 1) s += __shfl_xor_sync(0xffffffffu, s, m);
    float inv = 1.0f / fmaxf(sqrtf(s), 1e-12f);
    float2 o = make_float2(v.x * inv, v.y * inv);
    reinterpret_cast<float2*>(g_embn + (size_t)warp * KD)[lane] = o;

    __half2 h2 = __floats2half2_rn(o.x, o.y);
    int w; memcpy(&w, &h2, 4);
    int g  = warp >> 12;
    int el = warp & 4095;
    int et = el >> 7, er = el & 127;
    int ui = er * 32 + ((((lane >> 2)) ^ (er & 7)) << 2) + (lane & 3);
    g_embh[(size_t)(g * NTILES + et) * 4096 + ui] = w;
}

// ============================================================================
// Tensor-core argmax via mma.sync m16n8k16 (fp16 in, fp16 accum) + streaming
// margin candidate filter. z[n,g,c] = z[b*262144 + (g*64+c)*1024 + hw].
// Grid (128, 4), 256 threads, 2 CTAs/SM.
// Dyn smem: [0,512) margins | A 16KB @1024 | B0 @17408 | B1 @33792.
// ============================================================================
__global__ __launch_bounds__(256, 2)
void vq_mma_kernel(const float* __restrict__ z)
{
    extern __shared__ __align__(1024) char smem[];
    float* smarg = reinterpret_cast<float*>(smem);
    uint32_t sbase = smem_u32(smem);
    const uint32_t aA = sbase + 1024;
    const uint32_t aB[2] = { sbase + 17408, sbase + 33792 };

    const int tid   = threadIdx.x;
    const int g     = blockIdx.y;
    const int qbase = blockIdx.x * TQ;
    const char* ebase = reinterpret_cast<const char*>(
        g_embh + (size_t)g * NTILES * 4096);

    // ---- preload B(0) via cp.async (64B per thread) ----
    {
        uint32_t d = aB[0] + tid * 16;
        const char* s = ebase + tid * 16;
        #pragma unroll
        for (int i = 0; i < 4; i++) cp16(d + i * 4096, s + i * 4096);
        cp_commit();
    }

    // ---- build A tile (fp16, swizzled) + per-row norm ----
    {
        const int b   = qbase >> 10;
        const int hwb = qbase & 1023;
        const float* zb = z + (size_t)b * 262144 + (size_t)(g * 64) * 1024 + hwb;
        const int q  = tid & 127;
        const int ph = tid >> 7;                 // handles c-pairs ph*16..+15
        __half2* A2 = reinterpret_cast<__half2*>(smem + 1024);
        float n2 = 0.0f;
        #pragma unroll
        for (int i = 0; i < 16; i++) {
            int c = (ph * 16 + i) * 2;
            float v0 = zb[(size_t)c * 1024 + q];
            float v1 = zb[(size_t)(c + 1) * 1024 + q];
            n2 += v0 * v0 + v1 * v1;
            int ui = q * 32 + (((c >> 3) ^ (q & 7)) << 2) + ((c & 7) >> 1);
            A2[ui] = __floats2half2_rn(v0, v1);
        }
        if (ph == 0) smarg[q] = n2;
        __syncthreads();
        if (ph == 1) smarg[q] = 0.02f * sqrtf(smarg[q] + n2);
        cp_wait0();
        __syncthreads();
    }

    const int w  = tid >> 5;
    const int l  = tid & 31;
    const int qw = (w & 3) * 32;
    const int ew = (w >> 2) * 64;

    float rm[4], marg[4];
    int   rowg[4];
    #pragma unroll
    for (int qb = 0; qb < 2; qb++)
        #pragma unroll
        for (int h = 0; h < 2; h++) {
            int slot = qb * 2 + h;
            int rq = qw + qb * 16 + (l >> 2) + h * 8;
            rm[slot]   = -3.0e38f;
            marg[slot] = smarg[rq];
            rowg[slot] = (qbase + rq) * GR + g;
        }

    for (int t = 0; t < NTILES; t++) {
        // async prefetch of next B tile into the other buffer
        if (t + 1 < NTILES) {
            uint32_t d = aB[(t + 1) & 1] + tid * 16;
            const char* s = ebase + (size_t)(t + 1) * 16384 + tid * 16;
            #pragma unroll
            for (int i = 0; i < 4; i++) cp16(d + i * 4096, s + i * 4096);
            cp_commit();
        }

        uint32_t acc[2][8][2];
        #pragma unroll
        for (int qb = 0; qb < 2; qb++)
            #pragma unroll
            for (int eb = 0; eb < 8; eb++)
                { acc[qb][eb][0] = 0u; acc[qb][eb][1] = 0u; }

        const uint32_t base = aB[t & 1];
        #pragma unroll
        for (int ks = 0; ks < 4; ks++) {
            uint32_t RA[2][4];
            #pragma unroll
            for (int qb = 0; qb < 2; qb++) {
                int row = qw + qb * 16 + (l & 15);
                int blk = ks * 2 + (l >> 4);
                LDSM_X4(RA[qb], aA + row * 128 + ((blk ^ (row & 7)) << 4));
            }
            uint32_t RB[4][4];
            #pragma unroll
            for (int ebp = 0; ebp < 4; ebp++) {
                int row = ew + ebp * 16 + (l & 7) + ((l >> 4) << 3);
                int blk = ks * 2 + ((l >> 3) & 1);
                LDSM_X4(RB[ebp], base + row * 128 + ((blk ^ (row & 7)) << 4));
            }
            #pragma unroll
            for (int qb = 0; qb < 2; qb++)
                #pragma unroll
                for (int eb = 0; eb < 8; eb++)
                    mma16816_f16(acc[qb][eb], RA[qb], &RB[eb >> 1][(eb & 1) * 2]);
        }

        // ---- streaming argmax epilogue (half2 SIMD) ----
        #pragma unroll
        for (int qb = 0; qb < 2; qb++)
            #pragma unroll
            for (int h = 0; h < 2; h++) {
                const int slot = qb * 2 + h;
                __half2 mx2 = *reinterpret_cast<__half2*>(&acc[qb][0][h]);
                #pragma unroll
                for (int eb = 1; eb < 8; eb++)
                    mx2 = __hmax2(mx2, *reinterpret_cast<__half2*>(&acc[qb][eb][h]));
                float mxf = fmaxf(__low2float(mx2), __high2float(mx2));
                mxf = fmaxf(mxf, __shfl_xor_sync(0xffffffffu, mxf, 1));
                mxf = fmaxf(mxf, __shfl_xor_sync(0xffffffffu, mxf, 2));
                if (mxf > rm[slot]) rm[slot] = mxf;
                const float thrf = rm[slot] - marg[slot];
                const __half2 thr2 = __half2half2(__float2half_rd(thrf));
                #pragma unroll
                for (int eb = 0; eb < 8; eb++) {
                    __half2 v2 = *reinterpret_cast<__half2*>(&acc[qb][eb][h]);
                    if (!__hblt2(v2, thr2)) {
                        int e0 = t * NT + ew + eb * 8 + (l & 3) * 2;
                        float vlo = __low2float(v2);
                        float vhi = __high2float(v2);
                        if (vlo >= thrf) {
                            int sc = atomicAdd(&g_cnt[rowg[slot]], 1);
                            if (sc < CAP) g_cand[(size_t)rowg[slot] * CAP + sc] = e0;
                        }
                        if (vhi >= thrf) {
                            int sc = atomicAdd(&g_cnt[rowg[slot]], 1);
                            if (sc < CAP) g_cand[(size_t)rowg[slot] * CAP + sc] = e0 + 1;
                        }
                    }
                }
            }
        if (t + 1 < NTILES) cp_wait0();
        __syncthreads();
    }
}

// ============================================================================
// Rescore: exact fp32 dot over candidates, first-index tie-break.
// Overflowed rows (cnt > CAP) fall back to an exact full 4096-scan.
// Block: 256 threads, 8 consecutive n (one b), 32 rows; warp does 4 rows.
// ============================================================================
__global__ __launch_bounds__(256)
void rescore_kernel(const float* __restrict__ z, float* __restrict__ out_idx)
{
    __shared__ float zsh[256 * 9];   // [c][hwi] pad stride 9

    const int tid = threadIdx.x;
    const int n0  = blockIdx.x * 8;
    const int b   = n0 >> 10;
    const int hw0 = n0 & 1023;
    const float* zb = z + (size_t)b * 262144 + hw0;

    #pragma unroll
    for (int w = 0; w < 8; w++) {
        int idx = tid + w * 256;
        int c = idx >> 3, hwi = idx & 7;
        zsh[c * 9 + hwi] = zb[(size_t)c * 1024 + hwi];
    }
    __syncthreads();

    const int wid = tid >> 5, lane = tid & 31;
    for (int rr = 0; rr < 4; rr++) {
        int lr  = wid * 4 + rr;
        int hwi = lr >> 2;
        int g   = lr & 3;
        int n   = n0 + hwi;
        int row = n * GR + g;
        int cnt = g_cnt[row];
        const float* zr = zsh + (g * 64) * 9 + hwi;

        float bv = -3.0e38f;
        int   be = 0x7FFFFFFF;
        if (cnt > CAP) {
            // overflow: exact scan of all 4096 embeddings
            for (int e = lane; e < NEG; e += 32) {
                const float4* er = reinterpret_cast<const float4*>(
                    g_embn + ((size_t)(g * NEG + e)) * KD);
                float acc = 0.0f;
                #pragma unroll
                for (int kk = 0; kk < 16; kk++) {
                    float4 ev = er[kk];
                    acc = fmaf(zr[(kk * 4 + 0) * 9], ev.x, acc);
                    acc = fmaf(zr[(kk * 4 + 1) * 9], ev.y, acc);
                    acc = fmaf(zr[(kk * 4 + 2) * 9], ev.z, acc);
                    acc = fmaf(zr[(kk * 4 + 3) * 9], ev.w, acc);
                }
                if (acc > bv || (acc == bv && e < be)) { bv = acc; be = e; }
            }
        } else {
            for (int base = 0; base < cnt; base += 32) {
                int c = base + lane;
                if (c < cnt) {
                    int e = g_cand[(size_t)row * CAP + c];
                    const float4* er = reinterpret_cast<const float4*>(
                        g_embn + ((size_t)(g * NEG + e)) * KD);
                    float acc = 0.0f;
                    #pragma unroll
                    for (int kk = 0; kk < 16; kk++) {
                        float4 ev = er[kk];
                        acc = fmaf(zr[(kk * 4 + 0) * 9], ev.x, acc);
                        acc = fmaf(zr[(kk * 4 + 1) * 9], ev.y, acc);
                        acc = fmaf(zr[(kk * 4 + 2) * 9], ev.z, acc);
                        acc = fmaf(zr[(kk * 4 + 3) * 9], ev.w, acc);
                    }
                    if (acc > bv || (acc == bv && e < be)) { bv = acc; be = e; }
                }
            }
        }
        unsigned u = __float_as_uint(bv);
        u = ((int)u < 0) ? ~u : (u | 0x80000000u);
        unsigned m = __reduce_max_sync(0xffffffffu, u);
        unsigned bidm = (u == m) ? (unsigned)be : 0xFFFFFFFFu;
        unsigned bi = __reduce_min_sync(0xffffffffu, bidm);
        if (lane == 0) {
            g_idx[row] = (int)bi;
            out_idx[row] = (float)bi;
        }
    }
}

// ============================================================================
// quant: out[b, g*64+c, h, w] = embn[g*4096 + idx[n,g], c]
// ============================================================================
__global__ void quant_kernel(float* __restrict__ out)
{
    int o = blockIdx.x * blockDim.x + threadIdx.x;
    if (o >= 16 * 256 * 1024) return;
    int hw = o & 1023;
    int ch = (o >> 10) & 255;
    int b  = o >> 18;
    int gg = ch >> 6, c = ch & 63;
    int n  = (b << 10) + hw;
    int v  = g_idx[n * GR + gg];
    out[o] = g_embn[((size_t)((gg << 12) + v)) * KD + c];
}

// one-hot of idx[:, 3] + histogram
__global__ void scatter_kernel(float* __restrict__ out_me)
{
    int n = blockIdx.x * blockDim.x + threadIdx.x;
    if (n >= NQ) return;
    int v = g_idx[n * GR + 3];
    out_me[(size_t)n * NEG + v] = 1.0f;
    atomicAdd(&g_hist[v], 1);
}

__global__ void perp_kernel(float* __restrict__ out_p)
{
    __shared__ float red[32];
    int t = threadIdx.x;
    float s = 0.0f;
    for (int i = t; i < NEG; i += 1024) {
        float p = (float)g_hist[i] * (1.0f / 16384.0f);
        s += p * logf(p + 1e-10f);
    }
    #pragma unroll
    for (int m = 16; m >= 1; m >>= 1) s += __shfl_xor_sync(0xffffffffu, s, m);
    if ((t & 31) == 0) red[t >> 5] = s;
    __syncthreads();
    if (t < 32) {
        float x = red[t];
        #pragma unroll
        for (int m = 16; m >= 1; m >>= 1) x += __shfl_xor_sync(0xffffffffu, x, m);
        if (t == 0) out_p[0] = expf(-x);
    }
}

// ============================================================================
// Output layout (fp32, concatenated, 71,368,717 elements):
//   [0, 4194304)            quant
//   [4194304, +12)          vq_loss(4) commit_loss(4) codebook_usage(4) = zeros
//   [4194316]               perplexity
//   [4194317, +16384*4096)  min_encodings
//   [71303181, +65536)      idx (cast to float)
// ============================================================================
extern "C" void kernel_launch(void* const* d_in, const int* in_sizes, int n_in,
                              void* d_out, int out_size)
{
    const float* z   = (const float*)d_in[0];
    const float* emb = (const float*)d_in[1];
    float* out = (float*)d_out;

    const size_t QUANT   = (size_t)16 * 256 * 1024;          // 4194304
    const size_t PERP    = QUANT + 12;
    const size_t ME_OFF  = QUANT + 13;
    const size_t ME_SZ   = (size_t)NQ * NEG;                  // 67108864
    const size_t IDX_OFF = ME_OFF + ME_SZ;                    // 71303181

    const int SMEM = 50176;   // margins + A 16KB + 2x16KB B
    cudaFuncSetAttribute(vq_mma_kernel,
                         cudaFuncAttributeMaxDynamicSharedMemorySize, SMEM);

    // zero losses + perplexity slot + min_encodings (268 MB)
    cudaMemsetAsync(out + QUANT, 0, (13 + ME_SZ) * sizeof(float));

    init_kernel<<<256, 256>>>();
    embprep_kernel<<<2048, 256>>>(emb);

    dim3 agrid(NQ / TQ, GR);   // (128, 4)
    vq_mma_kernel<<<agrid, 256, SMEM>>>(z);

    rescore_kernel<<<NQ / 8, 256>>>(z, out + IDX_OFF);

    quant_kernel<<<16384, 256>>>(out);
    scatter_kernel<<<64, 256>>>(out + ME_OFF);
    perp_kernel<<<1, 1024>>>(out + PERP);
}